// round 14
// baseline (speedup 1.0000x reference)
#include <cuda_runtime.h>
#include <cuda_fp16.h>
#include <math.h>
#include <cstdint>

#define B_SZ 2
#define T_SZ 2048
#define NH   16
#define NKV  4
#define HD   128
#define MR   (B_SZ * T_SZ)   // 4096 rows
#define KC   2048            // inner dim (halves) of projection GEMMs

// ---------------- scratch (__device__ globals: allocation-free rule) --------
__device__ __half g_q   [MR * NH  * HD];   // head-dim pair-permuted (after rope)
__device__ __half g_k   [MR * NKV * HD];   // head-dim pair-permuted (after rope)
__device__ __half g_v   [MR * NKV * HD];   // natural
__device__ __half g_y   [MR * NH  * HD];   // pair-permuted (feeds final GEMM)
__device__ __half g_xh  [MR * 2048];       // x, fp16 + pair-permuted
__device__ __half g_wqkvT[3072 * 2048];    // [wq;wk;wv]^T, fp16 + pair-permuted
__device__ __half g_woT [2048 * 2048];     // wo^T, fp16 + pair-permuted

// pair-permutation within each 16-half k-group:
//   pair p (0..7) -> slot ((p&3)<<1)|(p>>2); element k -> k' below
__device__ __forceinline__ int pslot(int p) { return ((p & 3) << 1) | (p >> 2); }
__device__ __forceinline__ int kperm(int k) {
    return (k & ~15) | (pslot((k >> 1) & 7) << 1) | (k & 1);
}

// ---------------- PTX helpers (baseline compute_103-safe) -------------------
__device__ __forceinline__ void cp16(uint32_t s, const void* g) {
    asm volatile("cp.async.cg.shared.global [%0], [%1], 16;" :: "r"(s), "l"(g));
}
__device__ __forceinline__ void cp_commit() {
    asm volatile("cp.async.commit_group;" ::: "memory");
}
template <int N> __device__ __forceinline__ void cp_wait() {
    asm volatile("cp.async.wait_group %0;" :: "n"(N) : "memory");
}
// m16n8k16 fp16 mma, fp32 accum
__device__ __forceinline__ void mma_f16(float* c, const uint32_t* a, const uint32_t* b) {
    asm volatile(
        "mma.sync.aligned.m16n8k16.row.col.f32.f16.f16.f32 "
        "{%0,%1,%2,%3}, {%4,%5,%6,%7}, {%8,%9}, {%0,%1,%2,%3};"
        : "+f"(c[0]), "+f"(c[1]), "+f"(c[2]), "+f"(c[3])
        : "r"(a[0]), "r"(a[1]), "r"(a[2]), "r"(a[3]), "r"(b[0]), "r"(b[1]));
}
__device__ __forceinline__ uint32_t f2h2(float a, float b) {
    half2 h = __floats2half2_rn(a, b);
    return *(uint32_t*)&h;
}

// ---------------------------------------------------------------------------
// fp16 mma GEMM: C[M,N] = A[M,2048] @ BT[N,2048]^T (both fp16, pair-permuted k)
// CTA 128(M) x 256(N) x 32(K halves); 256 thr, 8 warps (2m x 4n), warp 64x64.
// 4-stage cp.async pipeline, distance-3 prefetch, single sync per iter.
// SPLIT: route 64-col groups to q/k (head-permuted) and v (natural), all fp16.
// ---------------------------------------------------------------------------
#define BM 128
#define BN 256
#define BK 32
#define PADH 40                               // halves per stage row
#define STG_HALVES ((BM + BN) * PADH)         // 15360
#define NSTG 4
#define GEMM_SMEM  (NSTG * STG_HALVES * 2)    // 122880 B

__device__ __forceinline__ void g_fill(uint32_t smb, int st, int ck, int tid,
                                       const __half* Ab, const __half* Bb) {
    uint32_t sa = smb + st * (STG_HALVES * 2);
    uint32_t sb = sa + BM * PADH * 2;
    const __half* Ac = Ab + ck * BK;
    const __half* Bc = Bb + ck * BK;
#pragma unroll
    for (int u = 0; u < 2; u++) {           // A: 128 rows x 4 cp16
        int idx = u * 256 + tid;
        int r = idx >> 2, c8 = (idx & 3) * 8;
        cp16(sa + (r * PADH + c8) * 2, Ac + (size_t)r * KC + c8);
    }
#pragma unroll
    for (int u = 0; u < 4; u++) {           // B: 256 rows x 4 cp16
        int idx = u * 256 + tid;
        int r = idx >> 2, c8 = (idx & 3) * 8;
        cp16(sb + (r * PADH + c8) * 2, Bc + (size_t)r * KC + c8);
    }
    cp_commit();
}

template <bool SPLIT>
__global__ void __launch_bounds__(256, 1)
gemm_h(const __half* __restrict__ A, const __half* __restrict__ BT,
       float* __restrict__ Cf, __half* __restrict__ Cq,
       __half* __restrict__ Ck, __half* __restrict__ Cv, int N) {
    extern __shared__ __half smh[];
    uint32_t smb = (uint32_t)__cvta_generic_to_shared(smh);

    const int tid  = threadIdx.x;
    const int lane = tid & 31;
    const int warp = tid >> 5;
    const int wm   = (warp >> 2) * 64;
    const int wn   = (warp & 3) * 64;
    const int bm   = blockIdx.y * BM;
    const int bn   = blockIdx.x * BN;

    const __half* Ab = A  + (size_t)bm * KC;
    const __half* Bb = BT + (size_t)bn * KC;

    float acc[4][8][4];
#pragma unroll
    for (int i = 0; i < 4; i++)
#pragma unroll
        for (int j = 0; j < 8; j++)
#pragma unroll
            for (int r = 0; r < 4; r++) acc[i][j][r] = 0.f;

    g_fill(smb, 0, 0, tid, Ab, Bb);
    g_fill(smb, 1, 1, tid, Ab, Bb);
    g_fill(smb, 2, 2, tid, Ab, Bb);

    const int lr = lane >> 2;
    const int lc = lane & 3;
    const int NCK = KC / BK;   // 64

    for (int i = 0; i < NCK; i++) {
        cp_wait<2>();
        __syncthreads();   // all warps done with stage (i-1)%4 AND stage i ready
        if (i + 3 < NCK) g_fill(smb, (i + 3) & 3, i + 3, tid, Ab, Bb);

        const __half* As = smh + (i & 3) * STG_HALVES;
        const __half* Bs = As + BM * PADH;

#pragma unroll
        for (int ks = 0; ks < 2; ks++) {      // two k16 chunks per BK=32
            uint32_t a[4][4], b[8][2];
#pragma unroll
            for (int mf = 0; mf < 4; mf++) {
                uint2 v0 = *(const uint2*)(As + (wm + mf * 16 + lr) * PADH + ks * 16 + 4 * lc);
                uint2 v1 = *(const uint2*)(As + (wm + mf * 16 + lr + 8) * PADH + ks * 16 + 4 * lc);
                a[mf][0] = v0.x; a[mf][1] = v1.x;
                a[mf][2] = v0.y; a[mf][3] = v1.y;
            }
#pragma unroll
            for (int nf = 0; nf < 8; nf++) {
                uint2 v = *(const uint2*)(Bs + (wn + nf * 8 + lr) * PADH + ks * 16 + 4 * lc);
                b[nf][0] = v.x; b[nf][1] = v.y;
            }
#pragma unroll
            for (int mf = 0; mf < 4; mf++)
#pragma unroll
                for (int nf = 0; nf < 8; nf++)
                    mma_f16(acc[mf][nf], a[mf], b[nf]);
        }
    }

    // ---- epilogue ----
    const int colbase = bn + wn;    // multiple of 64
    if (!SPLIT) {
#pragma unroll
        for (int mf = 0; mf < 4; mf++) {
            int row0 = bm + wm + mf * 16 + lr;
#pragma unroll
            for (int nf = 0; nf < 8; nf++) {
                int col = colbase + nf * 8 + lc * 2;
                *(float2*)(Cf + (size_t)row0 * N + col) =
                    make_float2(acc[mf][nf][0], acc[mf][nf][1]);
                *(float2*)(Cf + (size_t)(row0 + 8) * N + col) =
                    make_float2(acc[mf][nf][2], acc[mf][nf][3]);
            }
        }
    } else {
        __half* dst; int ldc; int cb; bool perm;
        if (colbase < 2048)      { dst = Cq; ldc = 2048; cb = colbase;        perm = true; }
        else if (colbase < 2560) { dst = Ck; ldc = 512;  cb = colbase - 2048; perm = true; }
        else                     { dst = Cv; ldc = 512;  cb = colbase - 2560; perm = false; }
#pragma unroll
        for (int mf = 0; mf < 4; mf++) {
            int row0 = bm + wm + mf * 16 + lr;
#pragma unroll
            for (int nf = 0; nf < 8; nf++) {
                int col = cb + nf * 8 + lc * 2;
                int colw = col;
                if (perm) {
                    int hb = col & ~127, hc = col & 127;
                    colw = hb + (hc & ~15) + pslot((hc >> 1) & 7) * 2;
                }
                half2 v01 = __halves2half2(__float2half(acc[mf][nf][0]),
                                           __float2half(acc[mf][nf][1]));
                half2 v23 = __halves2half2(__float2half(acc[mf][nf][2]),
                                           __float2half(acc[mf][nf][3]));
                *(half2*)(dst + (size_t)row0 * ldc + colw)       = v01;
                *(half2*)(dst + (size_t)(row0 + 8) * ldc + colw) = v23;
            }
        }
    }
}

// ---------------------------------------------------------------------------
// Weight transpose + fp16 + pair-permute: WT[n][kperm(k)] = h(W[k][n])
// ---------------------------------------------------------------------------
__global__ void transpose_h(const float* __restrict__ W, __half* __restrict__ WT,
                            int K, int N) {
    __shared__ float t[32][33];
    int n0 = blockIdx.x * 32, k0 = blockIdx.y * 32;
    int tx = threadIdx.x, ty = threadIdx.y;
#pragma unroll
    for (int i = 0; i < 4; i++)
        t[ty + 8 * i][tx] = W[(size_t)(k0 + ty + 8 * i) * N + n0 + tx];
    __syncthreads();
    int kp = kperm(k0 + tx);
#pragma unroll
    for (int i = 0; i < 4; i++)
        WT[(size_t)(n0 + ty + 8 * i) * K + kp] = __float2half(t[tx][ty + 8 * i]);
}

// x -> fp16, pair-permuted
__global__ void conv_x(const float* __restrict__ X, __half* __restrict__ XH, int n4) {
    int i = blockIdx.x * blockDim.x + threadIdx.x;
    if (i >= n4) return;
    float4 v = ((const float4*)X)[i];
    int f0 = i * 4;                       // multiple of 4 -> pair index even
    int base = f0 & ~15;
    int p0 = (f0 >> 1) & 7;               // even
    int s0 = pslot(p0), s1 = pslot(p0 + 1);
    *(half2*)(XH + base + s0 * 2) = __halves2half2(__float2half(v.x), __float2half(v.y));
    *(half2*)(XH + base + s1 * 2) = __halves2half2(__float2half(v.z), __float2half(v.w));
}

// ---------------------------------------------------------------------------
// In-place RoPE on fp16 pair-permuted [B*T, nheads*128]
// ---------------------------------------------------------------------------
__global__ void rope_h(__half* __restrict__ X, int nheads) {
    int idx = blockIdx.x * blockDim.x + threadIdx.x;
    int total = MR * 64 * nheads;
    if (idx >= total) return;
    int dp   = idx & 63;
    int rest = idx >> 6;
    int h    = rest % nheads;
    int bt   = rest / nheads;
    int t    = bt & (T_SZ - 1);

    float inv_freq = powf(10000.0f, -(float)(2 * dp) * (1.0f / 128.0f));
    float ang = (float)t * inv_freq;
    float sv, cv;
    sincosf(ang, &sv, &cv);

    __half* p = X + (size_t)bt * (nheads * HD) + h * HD;
    int a0 = kperm(dp), a1 = kperm(dp + 64);
    float x0 = __half2float(p[a0]), x1 = __half2float(p[a1]);
    p[a0] = __float2half(x0 * cv - x1 * sv);
    p[a1] = __float2half(x1 * cv + x0 * sv);
}

// ---------------------------------------------------------------------------
// fp16 tensor-core flash attention (m16n8k16), causal, GQA.
// CTA: 128 queries; KV tiles of 64; 8 warps, warp = 16 q rows x all keys.
// Double-buffered K/Vt; register-resident P; V prefetched LDG->regs at top,
// STS deferred past S+softmax (hides load latency under compute).
// Smem (halves): K0 @0 (64x136), K1 @8704, Vt0 @17408 (128x72), Vt1 @26624.
// Q staged transiently @0. Total 35840 halves = 71680 B.
// ---------------------------------------------------------------------------
#define KPADH 136
#define VPADH 72
#define FA_SMEM (35840 * 2)

__global__ void __launch_bounds__(256, 1)
flash_h(const __half* __restrict__ Q, const __half* __restrict__ K,
        const __half* __restrict__ V, __half* __restrict__ Y) {
    extern __shared__ __half smh[];
    uint32_t smb = (uint32_t)__cvta_generic_to_shared(smh);

    const int bi  = gridDim.x - 1 - blockIdx.x;   // big tiles first
    const int bh  = blockIdx.y;
    const int b   = bh >> 4, h = bh & 15;
    const int kvh = h >> 2;
    const int tid = threadIdx.x;
    const int warp = tid >> 5, lane = tid & 31;
    const int lr = lane >> 2, lc = lane & 3;

    const __half* kg0 = K + (size_t)(b * T_SZ) * 512 + kvh * 128;
    const __half* vg0 = V + (size_t)(b * T_SZ) * 512 + kvh * 128;

    // stage Q tile (fp16, pair-permuted) into smem @0: 128 x 128 halves
    const __half* qg = Q + (size_t)(b * T_SZ + bi * 128) * 2048 + h * 128;
#pragma unroll
    for (int it = 0; it < 8; it++) {
        int idx = it * 256 + tid;
        int r = idx >> 4, c8 = (idx & 15) * 8;
        cp16(smb + (r * KPADH + c8) * 2, qg + (size_t)r * 2048 + c8);
    }
    cp_commit();
    cp_wait<0>();
    __syncthreads();

    uint32_t qa[8][4];
#pragma unroll
    for (int ck = 0; ck < 8; ck++) {
        uint2 v0 = *(const uint2*)(smh + (warp * 16 + lr) * KPADH + ck * 16 + 4 * lc);
        uint2 v1 = *(const uint2*)(smh + (warp * 16 + lr + 8) * KPADH + ck * 16 + 4 * lc);
        qa[ck][0] = v0.x; qa[ck][1] = v1.x;
        qa[ck][2] = v0.y; qa[ck][3] = v1.y;
    }
    __syncthreads();   // all warps done reading Qs before K fills overwrite it

    // V-transpose thread mapping (fixed per thread)
    const int vd = (warp & 3) * 32 + lane;      // d: 0..127
    const int vt0 = (warp >> 2) * 4;            // t start: 0 or 4

    // ---- prologue: fill buffer 0 with kv tile 0 ----
    {
        const __half* kg = kg0;
#pragma unroll
        for (int it = 0; it < 4; it++) {
            int idx = it * 256 + tid;
            int r = idx >> 4, c8 = (idx & 15) * 8;
            cp16(smb + (r * KPADH + c8) * 2, kg + (size_t)r * 512 + c8);
        }
        cp_commit();
        const __half* vg = vg0;
        __half* Vt = smh + 17408;
#pragma unroll
        for (int it = 0; it < 8; it++) {
            int t4 = vt0 + it * 8;
            __half v0 = vg[(size_t)(t4 + 0) * 512 + vd];
            __half v1 = vg[(size_t)(t4 + 1) * 512 + vd];
            __half v2 = vg[(size_t)(t4 + 2) * 512 + vd];
            __half v3 = vg[(size_t)(t4 + 3) * 512 + vd];
            int p = t4 >> 1;
            int chb = (p >> 3) * 16;
            *(half2*)(Vt + vd * VPADH + chb + pslot(p & 7) * 2) = __halves2half2(v0, v1);
            *(half2*)(Vt + vd * VPADH + chb + pslot((p + 1) & 7) * 2) = __halves2half2(v2, v3);
        }
        cp_wait<0>();
        __syncthreads();
    }

    float o[16][4];
#pragma unroll
    for (int nf = 0; nf < 16; nf++)
        o[nf][0] = o[nf][1] = o[nf][2] = o[nf][3] = 0.f;
    float m0 = -1e30f, m1 = -1e30f, l0 = 0.f, l1 = 0.f;

    const float sc = 0.08838834764831845f;   // 1/sqrt(128)
    const int rlo = bi * 128 + warp * 16 + lr;
    const int jmax = 2 * bi + 1;

    for (int j = 0; j <= jmax; j++) {
        const int cur = j & 1;
        const bool pf = (j < jmax);

        // ---- prefetch tile j+1: K via cp.async; V via LDG -> registers ----
        __half vr[32];
        if (pf) {
            const int nx = cur ^ 1;
            const __half* kg = kg0 + (size_t)(j + 1) * 64 * 512;
#pragma unroll
            for (int it = 0; it < 4; it++) {
                int idx = it * 256 + tid;
                int r = idx >> 4, c8 = (idx & 15) * 8;
                cp16(smb + (nx * 8704 + r * KPADH + c8) * 2, kg + (size_t)r * 512 + c8);
            }
            cp_commit();
            const __half* vg = vg0 + (size_t)(j + 1) * 64 * 512;
#pragma unroll
            for (int it = 0; it < 8; it++) {
                int t4 = vt0 + it * 8;
                vr[it * 4 + 0] = vg[(size_t)(t4 + 0) * 512 + vd];
                vr[it * 4 + 1] = vg[(size_t)(t4 + 1) * 512 + vd];
                vr[it * 4 + 2] = vg[(size_t)(t4 + 2) * 512 + vd];
                vr[it * 4 + 3] = vg[(size_t)(t4 + 3) * 512 + vd];
            }
        }

        const __half* Ks = smh + cur * 8704;
        const __half* Vc = smh + 17408 + cur * 9216;

        // ---- S = Q K^T (warp: 16 x 64), 8 k16 chunks ----
        float sa[8][4];
#pragma unroll
        for (int nf = 0; nf < 8; nf++)
            sa[nf][0] = sa[nf][1] = sa[nf][2] = sa[nf][3] = 0.f;
#pragma unroll
        for (int ck = 0; ck < 8; ck++) {
            uint32_t bf[8][2];
#pragma unroll
            for (int nf = 0; nf < 8; nf++) {
                uint2 v = *(const uint2*)(Ks + (nf * 8 + lr) * KPADH + ck * 16 + 4 * lc);
                bf[nf][0] = v.x; bf[nf][1] = v.y;
            }
#pragma unroll
            for (int nf = 0; nf < 8; nf++)
                mma_f16(sa[nf], qa[ck], bf[nf]);
        }

        // ---- scale + causal mask ----
        const bool domask = (j >= 2 * bi);
#pragma unroll
        for (int nf = 0; nf < 8; nf++) {
            sa[nf][0] *= sc; sa[nf][1] *= sc;
            sa[nf][2] *= sc; sa[nf][3] *= sc;
            if (domask) {
                int c0 = j * 64 + nf * 8 + 2 * lc;
                if (c0 > rlo)         sa[nf][0] = -1e30f;
                if (c0 + 1 > rlo)     sa[nf][1] = -1e30f;
                if (c0 > rlo + 8)     sa[nf][2] = -1e30f;
                if (c0 + 1 > rlo + 8) sa[nf][3] = -1e30f;
            }
        }

        // ---- online softmax (2 rows/thread, quad reduce); P stays in sa ----
        float mx0 = -1e30f, mx1 = -1e30f;
#pragma unroll
        for (int nf = 0; nf < 8; nf++) {
            mx0 = fmaxf(mx0, fmaxf(sa[nf][0], sa[nf][1]));
            mx1 = fmaxf(mx1, fmaxf(sa[nf][2], sa[nf][3]));
        }
        mx0 = fmaxf(mx0, __shfl_xor_sync(0xffffffffu, mx0, 1));
        mx0 = fmaxf(mx0, __shfl_xor_sync(0xffffffffu, mx0, 2));
        mx1 = fmaxf(mx1, __shfl_xor_sync(0xffffffffu, mx1, 1));
        mx1 = fmaxf(mx1, __shfl_xor_sync(0xffffffffu, mx1, 2));

        float mn0 = fmaxf(m0, mx0), mn1 = fmaxf(m1, mx1);
        float al0 = __expf(m0 - mn0), al1 = __expf(m1 - mn1);
        float s0 = 0.f, s1 = 0.f;
#pragma unroll
        for (int nf = 0; nf < 8; nf++) {
            float p0 = __expf(sa[nf][0] - mn0);
            float p1 = __expf(sa[nf][1] - mn0);
            float p2 = __expf(sa[nf][2] - mn1);
            float p3 = __expf(sa[nf][3] - mn1);
            s0 += p0 + p1; s1 += p2 + p3;
            sa[nf][0] = p0; sa[nf][1] = p1; sa[nf][2] = p2; sa[nf][3] = p3;
        }
        s0 += __shfl_xor_sync(0xffffffffu, s0, 1);
        s0 += __shfl_xor_sync(0xffffffffu, s0, 2);
        s1 += __shfl_xor_sync(0xffffffffu, s1, 1);
        s1 += __shfl_xor_sync(0xffffffffu, s1, 2);
        l0 = l0 * al0 + s0; m0 = mn0;
        l1 = l1 * al1 + s1; m1 = mn1;
#pragma unroll
        for (int nf = 0; nf < 16; nf++) {
            o[nf][0] *= al0; o[nf][1] *= al0;
            o[nf][2] *= al1; o[nf][3] *= al1;
        }

        // ---- deferred V STS: loads issued ~2000 cyc ago, now landed ----
        if (pf) {
            __half* Vt = smh + 17408 + (cur ^ 1) * 9216;
#pragma unroll
            for (int it = 0; it < 8; it++) {
                int t4 = vt0 + it * 8;
                int p = t4 >> 1;
                int chb = (p >> 3) * 16;
                *(half2*)(Vt + vd * VPADH + chb + pslot(p & 7) * 2) =
                    __halves2half2(vr[it * 4 + 0], vr[it * 4 + 1]);
                *(half2*)(Vt + vd * VPADH + chb + pslot((p + 1) & 7) * 2) =
                    __halves2half2(vr[it * 4 + 2], vr[it * 4 + 3]);
            }
        }

        // ---- O += P V (warp: 16 x 128); P packed directly from registers ----
#pragma unroll
        for (int ck = 0; ck < 4; ck++) {
            uint32_t pa[4];
            pa[0] = f2h2(sa[2 * ck][0],     sa[2 * ck][1]);
            pa[1] = f2h2(sa[2 * ck][2],     sa[2 * ck][3]);
            pa[2] = f2h2(sa[2 * ck + 1][0], sa[2 * ck + 1][1]);
            pa[3] = f2h2(sa[2 * ck + 1][2], sa[2 * ck + 1][3]);
#pragma unroll
            for (int nf = 0; nf < 16; nf++) {
                uint2 bv = *(const uint2*)(Vc + (nf * 8 + lr) * VPADH + ck * 16 + 4 * lc);
                uint32_t bb[2] = {bv.x, bv.y};
                mma_f16(o[nf], pa, bb);
            }
        }

        cp_wait<0>();
        __syncthreads();   // tile j+1 ready; all warps done with buffer cur
    }

    // ---- normalize + store y fp16, pair-permuted (feeds final GEMM) ----
    float inv0 = 1.f / l0, inv1 = 1.f / l1;
    __half* y0 = Y + (size_t)(b * T_SZ + bi * 128 + warp * 16 + lr) * 2048 + h * 128;
    __half* y1 = y0 + 8 * 2048;
#pragma unroll
    for (int nf = 0; nf < 16; nf++) {
        int hc = nf * 8 + 2 * lc;
        int colw = (hc & ~15) + pslot((hc >> 1) & 7) * 2;
        *(half2*)(y0 + colw) = __halves2half2(__float2half(o[nf][0] * inv0),
                                              __float2half(o[nf][1] * inv0));
        *(half2*)(y1 + colw) = __halves2half2(__float2half(o[nf][2] * inv1),
                                              __float2half(o[nf][3] * inv1));
    }
}

// ---------------------------------------------------------------------------
extern "C" void kernel_launch(void* const* d_in, const int* in_sizes, int n_in,
                              void* d_out, int out_size) {
    const float* x  = (const float*)d_in[0];
    const float* wq = (const float*)d_in[1];
    const float* wk = (const float*)d_in[2];
    const float* wv = (const float*)d_in[3];
    const float* wo = (const float*)d_in[4];
    float* out = (float*)d_out;

    __half *qp, *kp, *vp, *yp, *xh, *wqkvT, *woT;
    cudaGetSymbolAddress((void**)&qp,    g_q);
    cudaGetSymbolAddress((void**)&kp,    g_k);
    cudaGetSymbolAddress((void**)&vp,    g_v);
    cudaGetSymbolAddress((void**)&yp,    g_y);
    cudaGetSymbolAddress((void**)&xh,    g_xh);
    cudaGetSymbolAddress((void**)&wqkvT, g_wqkvT);
    cudaGetSymbolAddress((void**)&woT,   g_woT);

    cudaFuncSetAttribute(gemm_h<false>, cudaFuncAttributeMaxDynamicSharedMemorySize, GEMM_SMEM);
    cudaFuncSetAttribute(gemm_h<true>,  cudaFuncAttributeMaxDynamicSharedMemorySize, GEMM_SMEM);
    cudaFuncSetAttribute(flash_h, cudaFuncAttributeMaxDynamicSharedMemorySize, FA_SMEM);

    dim3 tb(32, 8);
    transpose_h<<<dim3(2048 / 32, 2048 / 32), tb>>>(wq, wqkvT,               2048, 2048);
    transpose_h<<<dim3(512  / 32, 2048 / 32), tb>>>(wk, wqkvT + 2048 * 2048, 2048, 512);
    transpose_h<<<dim3(512  / 32, 2048 / 32), tb>>>(wv, wqkvT + 2560 * 2048, 2048, 512);
    transpose_h<<<dim3(2048 / 32, 2048 / 32), tb>>>(wo, woT,                 2048, 2048);

    conv_x<<<(MR * 2048 / 4 + 255) / 256, 256>>>(x, xh, MR * 2048 / 4);

    // Fused QKV projection (N = 3072); q,k head-permuted fp16; v natural fp16
    gemm_h<true><<<dim3(3072 / BN, MR / BM), 256, GEMM_SMEM>>>(
        xh, wqkvT, nullptr, qp, kp, vp, 3072);

    rope_h<<<(MR * NH  * 64 + 255) / 256, 256>>>(qp, NH);
    rope_h<<<(MR * NKV * 64 + 255) / 256, 256>>>(kp, NKV);

    // fp16 tensor-core causal GQA flash attention (double-buffered)
    flash_h<<<dim3(T_SZ / 128, B_SZ * NH), 256, FA_SMEM>>>(qp, kp, vp, yp);

    // Output projection (fp32 out)
    gemm_h<false><<<dim3(2048 / BN, MR / BM), 256, GEMM_SMEM>>>(
        yp, woT, out, nullptr, nullptr, nullptr, 2048);
}

// round 15
// speedup vs baseline: 1.0559x; 1.0559x over previous
#include <cuda_runtime.h>
#include <cuda_fp16.h>
#include <math.h>
#include <cstdint>

#define B_SZ 2
#define T_SZ 2048
#define NH   16
#define NKV  4
#define HD   128
#define MR   (B_SZ * T_SZ)   // 4096 rows
#define KC   2048            // inner dim (halves) of projection GEMMs

// ---------------- scratch (__device__ globals: allocation-free rule) --------
__device__ __half g_q   [MR * NH  * HD];   // head-dim pair-permuted (after rope)
__device__ __half g_k   [MR * NKV * HD];   // head-dim pair-permuted (after rope)
__device__ __half g_v   [MR * NKV * HD];   // natural
__device__ __half g_y   [MR * NH  * HD];   // pair-permuted (feeds final GEMM)
__device__ __half g_xh  [MR * 2048];       // x, fp16 + pair-permuted
__device__ __half g_wqkvT[3072 * 2048];    // [wq;wk;wv]^T, fp16 + pair-permuted
__device__ __half g_woT [2048 * 2048];     // wo^T, fp16 + pair-permuted

// pair-permutation within each 16-half k-group:
//   pair p (0..7) -> slot ((p&3)<<1)|(p>>2); element k -> k' below
__device__ __forceinline__ int pslot(int p) { return ((p & 3) << 1) | (p >> 2); }
__device__ __forceinline__ int kperm(int k) {
    return (k & ~15) | (pslot((k >> 1) & 7) << 1) | (k & 1);
}

// ---------------- PTX helpers (baseline compute_103-safe) -------------------
__device__ __forceinline__ void cp16(uint32_t s, const void* g) {
    asm volatile("cp.async.cg.shared.global [%0], [%1], 16;" :: "r"(s), "l"(g));
}
__device__ __forceinline__ void cp_commit() {
    asm volatile("cp.async.commit_group;" ::: "memory");
}
template <int N> __device__ __forceinline__ void cp_wait() {
    asm volatile("cp.async.wait_group %0;" :: "n"(N) : "memory");
}
// m16n8k16 fp16 mma, fp32 accum
__device__ __forceinline__ void mma_f16(float* c, const uint32_t* a, const uint32_t* b) {
    asm volatile(
        "mma.sync.aligned.m16n8k16.row.col.f32.f16.f16.f32 "
        "{%0,%1,%2,%3}, {%4,%5,%6,%7}, {%8,%9}, {%0,%1,%2,%3};"
        : "+f"(c[0]), "+f"(c[1]), "+f"(c[2]), "+f"(c[3])
        : "r"(a[0]), "r"(a[1]), "r"(a[2]), "r"(a[3]), "r"(b[0]), "r"(b[1]));
}
__device__ __forceinline__ uint32_t f2h2(float a, float b) {
    half2 h = __floats2half2_rn(a, b);
    return *(uint32_t*)&h;
}

// ---------------------------------------------------------------------------
// fp16 mma GEMM: C[M,N] = A[M,2048] @ BT[N,2048]^T (both fp16, pair-permuted k)
// CTA 128(M) x 256(N) x 32(K halves); 256 thr, 8 warps (2m x 4n), warp 64x64.
// 3-stage cp.async pipeline, one sync per iter (bottom sync is redundant).
// SPLIT: route 64-col groups to q/k (head-permuted) and v (natural), all fp16.
// ---------------------------------------------------------------------------
#define BM 128
#define BN 256
#define BK 32
#define PADH 40                               // halves per stage row
#define STG_HALVES ((BM + BN) * PADH)         // 15360
#define GEMM_SMEM  (3 * STG_HALVES * 2)       // 92160 B

__device__ __forceinline__ void g_fill(uint32_t smb, int st, int ck, int tid,
                                       const __half* Ab, const __half* Bb) {
    uint32_t sa = smb + st * (STG_HALVES * 2);
    uint32_t sb = sa + BM * PADH * 2;
    const __half* Ac = Ab + ck * BK;
    const __half* Bc = Bb + ck * BK;
#pragma unroll
    for (int u = 0; u < 2; u++) {           // A: 128 rows x 4 cp16
        int idx = u * 256 + tid;
        int r = idx >> 2, c8 = (idx & 3) * 8;
        cp16(sa + (r * PADH + c8) * 2, Ac + (size_t)r * KC + c8);
    }
#pragma unroll
    for (int u = 0; u < 4; u++) {           // B: 256 rows x 4 cp16
        int idx = u * 256 + tid;
        int r = idx >> 2, c8 = (idx & 3) * 8;
        cp16(sb + (r * PADH + c8) * 2, Bc + (size_t)r * KC + c8);
    }
    cp_commit();
}

template <bool SPLIT>
__global__ void __launch_bounds__(256, 1)
gemm_h(const __half* __restrict__ A, const __half* __restrict__ BT,
       float* __restrict__ Cf, __half* __restrict__ Cq,
       __half* __restrict__ Ck, __half* __restrict__ Cv, int N) {
    extern __shared__ __half smh[];
    uint32_t smb = (uint32_t)__cvta_generic_to_shared(smh);

    const int tid  = threadIdx.x;
    const int lane = tid & 31;
    const int warp = tid >> 5;
    const int wm   = (warp >> 2) * 64;
    const int wn   = (warp & 3) * 64;
    const int bm   = blockIdx.y * BM;
    const int bn   = blockIdx.x * BN;

    const __half* Ab = A  + (size_t)bm * KC;
    const __half* Bb = BT + (size_t)bn * KC;

    float acc[4][8][4];
#pragma unroll
    for (int i = 0; i < 4; i++)
#pragma unroll
        for (int j = 0; j < 8; j++)
#pragma unroll
            for (int r = 0; r < 4; r++) acc[i][j][r] = 0.f;

    g_fill(smb, 0, 0, tid, Ab, Bb);
    g_fill(smb, 1, 1, tid, Ab, Bb);

    const int lr = lane >> 2;
    const int lc = lane & 3;
    const int NCK = KC / BK;   // 64

    for (int i = 0; i < NCK; i++) {
        cp_wait<1>();
        __syncthreads();   // stage i ready AND all warps done with stage (i-1)%3
        if (i + 2 < NCK) g_fill(smb, (i + 2) % 3, i + 2, tid, Ab, Bb);

        const __half* As = smh + (i % 3) * STG_HALVES;
        const __half* Bs = As + BM * PADH;

#pragma unroll
        for (int ks = 0; ks < 2; ks++) {      // two k16 chunks per BK=32
            uint32_t a[4][4], b[8][2];
#pragma unroll
            for (int mf = 0; mf < 4; mf++) {
                uint2 v0 = *(const uint2*)(As + (wm + mf * 16 + lr) * PADH + ks * 16 + 4 * lc);
                uint2 v1 = *(const uint2*)(As + (wm + mf * 16 + lr + 8) * PADH + ks * 16 + 4 * lc);
                a[mf][0] = v0.x; a[mf][1] = v1.x;
                a[mf][2] = v0.y; a[mf][3] = v1.y;
            }
#pragma unroll
            for (int nf = 0; nf < 8; nf++) {
                uint2 v = *(const uint2*)(Bs + (wn + nf * 8 + lr) * PADH + ks * 16 + 4 * lc);
                b[nf][0] = v.x; b[nf][1] = v.y;
            }
#pragma unroll
            for (int mf = 0; mf < 4; mf++)
#pragma unroll
                for (int nf = 0; nf < 8; nf++)
                    mma_f16(acc[mf][nf], a[mf], b[nf]);
        }
    }

    // ---- epilogue ----
    const int colbase = bn + wn;    // multiple of 64
    if (!SPLIT) {
#pragma unroll
        for (int mf = 0; mf < 4; mf++) {
            int row0 = bm + wm + mf * 16 + lr;
#pragma unroll
            for (int nf = 0; nf < 8; nf++) {
                int col = colbase + nf * 8 + lc * 2;
                *(float2*)(Cf + (size_t)row0 * N + col) =
                    make_float2(acc[mf][nf][0], acc[mf][nf][1]);
                *(float2*)(Cf + (size_t)(row0 + 8) * N + col) =
                    make_float2(acc[mf][nf][2], acc[mf][nf][3]);
            }
        }
    } else {
        __half* dst; int ldc; int cb; bool perm;
        if (colbase < 2048)      { dst = Cq; ldc = 2048; cb = colbase;        perm = true; }
        else if (colbase < 2560) { dst = Ck; ldc = 512;  cb = colbase - 2048; perm = true; }
        else                     { dst = Cv; ldc = 512;  cb = colbase - 2560; perm = false; }
#pragma unroll
        for (int mf = 0; mf < 4; mf++) {
            int row0 = bm + wm + mf * 16 + lr;
#pragma unroll
            for (int nf = 0; nf < 8; nf++) {
                int col = cb + nf * 8 + lc * 2;
                int colw = col;
                if (perm) {
                    int hb = col & ~127, hc = col & 127;
                    colw = hb + (hc & ~15) + pslot((hc >> 1) & 7) * 2;
                }
                half2 v01 = __halves2half2(__float2half(acc[mf][nf][0]),
                                           __float2half(acc[mf][nf][1]));
                half2 v23 = __halves2half2(__float2half(acc[mf][nf][2]),
                                           __float2half(acc[mf][nf][3]));
                *(half2*)(dst + (size_t)row0 * ldc + colw)       = v01;
                *(half2*)(dst + (size_t)(row0 + 8) * ldc + colw) = v23;
            }
        }
    }
}

// ---------------------------------------------------------------------------
// Weight transpose + fp16 + pair-permute: WT[n][kperm(k)] = h(W[k][n])
// ---------------------------------------------------------------------------
__global__ void transpose_h(const float* __restrict__ W, __half* __restrict__ WT,
                            int K, int N) {
    __shared__ float t[32][33];
    int n0 = blockIdx.x * 32, k0 = blockIdx.y * 32;
    int tx = threadIdx.x, ty = threadIdx.y;
#pragma unroll
    for (int i = 0; i < 4; i++)
        t[ty + 8 * i][tx] = W[(size_t)(k0 + ty + 8 * i) * N + n0 + tx];
    __syncthreads();
    int kp = kperm(k0 + tx);
#pragma unroll
    for (int i = 0; i < 4; i++)
        WT[(size_t)(n0 + ty + 8 * i) * K + kp] = __float2half(t[tx][ty + 8 * i]);
}

// x -> fp16, pair-permuted
__global__ void conv_x(const float* __restrict__ X, __half* __restrict__ XH, int n4) {
    int i = blockIdx.x * blockDim.x + threadIdx.x;
    if (i >= n4) return;
    float4 v = ((const float4*)X)[i];
    int f0 = i * 4;                       // multiple of 4 -> pair index even
    int base = f0 & ~15;
    int p0 = (f0 >> 1) & 7;               // even
    int s0 = pslot(p0), s1 = pslot(p0 + 1);
    *(half2*)(XH + base + s0 * 2) = __halves2half2(__float2half(v.x), __float2half(v.y));
    *(half2*)(XH + base + s1 * 2) = __halves2half2(__float2half(v.z), __float2half(v.w));
}

// ---------------------------------------------------------------------------
// In-place RoPE on fp16 pair-permuted [B*T, nheads*128]
// ---------------------------------------------------------------------------
__global__ void rope_h(__half* __restrict__ X, int nheads) {
    int idx = blockIdx.x * blockDim.x + threadIdx.x;
    int total = MR * 64 * nheads;
    if (idx >= total) return;
    int dp   = idx & 63;
    int rest = idx >> 6;
    int h    = rest % nheads;
    int bt   = rest / nheads;
    int t    = bt & (T_SZ - 1);

    float inv_freq = powf(10000.0f, -(float)(2 * dp) * (1.0f / 128.0f));
    float ang = (float)t * inv_freq;
    float sv, cv;
    sincosf(ang, &sv, &cv);

    __half* p = X + (size_t)bt * (nheads * HD) + h * HD;
    int a0 = kperm(dp), a1 = kperm(dp + 64);
    float x0 = __half2float(p[a0]), x1 = __half2float(p[a1]);
    p[a0] = __float2half(x0 * cv - x1 * sv);
    p[a1] = __float2half(x1 * cv + x0 * sv);
}

// ---------------------------------------------------------------------------
// fp16 tensor-core flash attention (m16n8k16), causal, GQA.
// CTA: 128 queries; KV tiles of 128 (halves per-tile overheads vs 64);
// 8 warps, warp = 16 q rows x all 128 keys. Double-buffered K/Vt;
// register-resident P. Mask only on the j == bi diagonal tile.
// Smem (halves): K0 @0 (128x136), K1 @17408, Vt0 @34816 (128x136), Vt1 @52224.
// Q staged transiently @0. Total 69632 halves = 139264 B.
// ---------------------------------------------------------------------------
#define KPADH 136
#define VPADH 136
#define KBUF  17408
#define FA_SMEM (69632 * 2)

__global__ void __launch_bounds__(256, 1)
flash_h(const __half* __restrict__ Q, const __half* __restrict__ K,
        const __half* __restrict__ V, __half* __restrict__ Y) {
    extern __shared__ __half smh[];
    uint32_t smb = (uint32_t)__cvta_generic_to_shared(smh);

    const int bi  = gridDim.x - 1 - blockIdx.x;   // big tiles first
    const int bh  = blockIdx.y;
    const int b   = bh >> 4, h = bh & 15;
    const int kvh = h >> 2;
    const int tid = threadIdx.x;
    const int warp = tid >> 5, lane = tid & 31;
    const int lr = lane >> 2, lc = lane & 3;

    const __half* kg0 = K + (size_t)(b * T_SZ) * 512 + kvh * 128;
    const __half* vg0 = V + (size_t)(b * T_SZ) * 512 + kvh * 128;

    // stage Q tile (fp16, pair-permuted) into smem @0: 128 x 128 halves
    const __half* qg = Q + (size_t)(b * T_SZ + bi * 128) * 2048 + h * 128;
#pragma unroll
    for (int it = 0; it < 8; it++) {
        int idx = it * 256 + tid;
        int r = idx >> 4, c8 = (idx & 15) * 8;
        cp16(smb + (r * KPADH + c8) * 2, qg + (size_t)r * 2048 + c8);
    }
    cp_commit();
    cp_wait<0>();
    __syncthreads();

    uint32_t qa[8][4];
#pragma unroll
    for (int ck = 0; ck < 8; ck++) {
        uint2 v0 = *(const uint2*)(smh + (warp * 16 + lr) * KPADH + ck * 16 + 4 * lc);
        uint2 v1 = *(const uint2*)(smh + (warp * 16 + lr + 8) * KPADH + ck * 16 + 4 * lc);
        qa[ck][0] = v0.x; qa[ck][1] = v1.x;
        qa[ck][2] = v0.y; qa[ck][3] = v1.y;
    }
    __syncthreads();   // all warps done reading Qs before K fills overwrite it

    // V-transpose thread mapping (fixed per thread)
    const int vd = (warp & 3) * 32 + lane;      // d: 0..127
    const int vt0 = (warp >> 2) * 4;            // t start: 0 or 4

    // ---- prologue: fill buffer 0 with kv tile 0 (128 rows) ----
    {
        const __half* kg = kg0;
#pragma unroll
        for (int it = 0; it < 8; it++) {
            int idx = it * 256 + tid;
            int r = idx >> 4, c8 = (idx & 15) * 8;
            cp16(smb + (r * KPADH + c8) * 2, kg + (size_t)r * 512 + c8);
        }
        cp_commit();
        const __half* vg = vg0;
        __half* Vt = smh + 2 * KBUF;
#pragma unroll
        for (int it = 0; it < 16; it++) {
            int t4 = vt0 + it * 8;
            __half v0 = vg[(size_t)(t4 + 0) * 512 + vd];
            __half v1 = vg[(size_t)(t4 + 1) * 512 + vd];
            __half v2 = vg[(size_t)(t4 + 2) * 512 + vd];
            __half v3 = vg[(size_t)(t4 + 3) * 512 + vd];
            int p = t4 >> 1;
            int chb = (p >> 3) * 16;
            *(half2*)(Vt + vd * VPADH + chb + pslot(p & 7) * 2) = __halves2half2(v0, v1);
            *(half2*)(Vt + vd * VPADH + chb + pslot((p + 1) & 7) * 2) = __halves2half2(v2, v3);
        }
        cp_wait<0>();
        __syncthreads();
    }

    float o[16][4];
#pragma unroll
    for (int nf = 0; nf < 16; nf++)
        o[nf][0] = o[nf][1] = o[nf][2] = o[nf][3] = 0.f;
    float m0 = -1e30f, m1 = -1e30f, l0 = 0.f, l1 = 0.f;

    const float sc = 0.08838834764831845f;   // 1/sqrt(128)
    const int rlo = bi * 128 + warp * 16 + lr;

    for (int j = 0; j <= bi; j++) {
        const int cur = j & 1;

        // ---- prefetch tile j+1 into the other buffer ----
        if (j < bi) {
            const int nx = cur ^ 1;
            const __half* kg = kg0 + (size_t)(j + 1) * 128 * 512;
#pragma unroll
            for (int it = 0; it < 8; it++) {
                int idx = it * 256 + tid;
                int r = idx >> 4, c8 = (idx & 15) * 8;
                cp16(smb + (nx * KBUF + r * KPADH + c8) * 2, kg + (size_t)r * 512 + c8);
            }
            cp_commit();
            const __half* vg = vg0 + (size_t)(j + 1) * 128 * 512;
            __half* Vt = smh + 2 * KBUF + nx * KBUF;
#pragma unroll
            for (int it = 0; it < 16; it++) {
                int t4 = vt0 + it * 8;
                __half v0 = vg[(size_t)(t4 + 0) * 512 + vd];
                __half v1 = vg[(size_t)(t4 + 1) * 512 + vd];
                __half v2 = vg[(size_t)(t4 + 2) * 512 + vd];
                __half v3 = vg[(size_t)(t4 + 3) * 512 + vd];
                int p = t4 >> 1;
                int chb = (p >> 3) * 16;
                *(half2*)(Vt + vd * VPADH + chb + pslot(p & 7) * 2) = __halves2half2(v0, v1);
                *(half2*)(Vt + vd * VPADH + chb + pslot((p + 1) & 7) * 2) = __halves2half2(v2, v3);
            }
        }

        const __half* Ks = smh + cur * KBUF;
        const __half* Vc = smh + 2 * KBUF + cur * KBUF;

        // ---- S = Q K^T (warp: 16 x 128), two nf-halves of 8 accumulators ----
        float sa[16][4];
#pragma unroll
        for (int nf = 0; nf < 16; nf++)
            sa[nf][0] = sa[nf][1] = sa[nf][2] = sa[nf][3] = 0.f;
#pragma unroll
        for (int half = 0; half < 2; half++) {
#pragma unroll
            for (int ck = 0; ck < 8; ck++) {
                uint32_t bf[8][2];
#pragma unroll
                for (int nf = 0; nf < 8; nf++) {
                    uint2 v = *(const uint2*)(Ks + ((half * 8 + nf) * 8 + lr) * KPADH + ck * 16 + 4 * lc);
                    bf[nf][0] = v.x; bf[nf][1] = v.y;
                }
#pragma unroll
                for (int nf = 0; nf < 8; nf++)
                    mma_f16(sa[half * 8 + nf], qa[ck], bf[nf]);
            }
        }

        // ---- scale + causal mask (diagonal tile only) ----
        const bool domask = (j == bi);
#pragma unroll
        for (int nf = 0; nf < 16; nf++) {
            sa[nf][0] *= sc; sa[nf][1] *= sc;
            sa[nf][2] *= sc; sa[nf][3] *= sc;
            if (domask) {
                int c0 = j * 128 + nf * 8 + 2 * lc;
                if (c0 > rlo)         sa[nf][0] = -1e30f;
                if (c0 + 1 > rlo)     sa[nf][1] = -1e30f;
                if (c0 > rlo + 8)     sa[nf][2] = -1e30f;
                if (c0 + 1 > rlo + 8) sa[nf][3] = -1e30f;
            }
        }

        // ---- online softmax (2 rows/thread, quad reduce); P stays in sa ----
        float mx0 = -1e30f, mx1 = -1e30f;
#pragma unroll
        for (int nf = 0; nf < 16; nf++) {
            mx0 = fmaxf(mx0, fmaxf(sa[nf][0], sa[nf][1]));
            mx1 = fmaxf(mx1, fmaxf(sa[nf][2], sa[nf][3]));
        }
        mx0 = fmaxf(mx0, __shfl_xor_sync(0xffffffffu, mx0, 1));
        mx0 = fmaxf(mx0, __shfl_xor_sync(0xffffffffu, mx0, 2));
        mx1 = fmaxf(mx1, __shfl_xor_sync(0xffffffffu, mx1, 1));
        mx1 = fmaxf(mx1, __shfl_xor_sync(0xffffffffu, mx1, 2));

        float mn0 = fmaxf(m0, mx0), mn1 = fmaxf(m1, mx1);
        float al0 = __expf(m0 - mn0), al1 = __expf(m1 - mn1);
        float s0 = 0.f, s1 = 0.f;
#pragma unroll
        for (int nf = 0; nf < 16; nf++) {
            float p0 = __expf(sa[nf][0] - mn0);
            float p1 = __expf(sa[nf][1] - mn0);
            float p2 = __expf(sa[nf][2] - mn1);
            float p3 = __expf(sa[nf][3] - mn1);
            s0 += p0 + p1; s1 += p2 + p3;
            sa[nf][0] = p0; sa[nf][1] = p1; sa[nf][2] = p2; sa[nf][3] = p3;
        }
        s0 += __shfl_xor_sync(0xffffffffu, s0, 1);
        s0 += __shfl_xor_sync(0xffffffffu, s0, 2);
        s1 += __shfl_xor_sync(0xffffffffu, s1, 1);
        s1 += __shfl_xor_sync(0xffffffffu, s1, 2);
        l0 = l0 * al0 + s0; m0 = mn0;
        l1 = l1 * al1 + s1; m1 = mn1;
#pragma unroll
        for (int nf = 0; nf < 16; nf++) {
            o[nf][0] *= al0; o[nf][1] *= al0;
            o[nf][2] *= al1; o[nf][3] *= al1;
        }

        // ---- O += P V (warp: 16 x 128); P packed from registers.
        //      k16 chunk ck covers t 16ck..16ck+15 = S-tiles 2ck, 2ck+1 ----
#pragma unroll
        for (int ck = 0; ck < 8; ck++) {
            uint32_t pa[4];
            pa[0] = f2h2(sa[2 * ck][0],     sa[2 * ck][1]);
            pa[1] = f2h2(sa[2 * ck][2],     sa[2 * ck][3]);
            pa[2] = f2h2(sa[2 * ck + 1][0], sa[2 * ck + 1][1]);
            pa[3] = f2h2(sa[2 * ck + 1][2], sa[2 * ck + 1][3]);
#pragma unroll
            for (int nf = 0; nf < 16; nf++) {
                uint2 bv = *(const uint2*)(Vc + (nf * 8 + lr) * VPADH + ck * 16 + 4 * lc);
                uint32_t bb[2] = {bv.x, bv.y};
                mma_f16(o[nf], pa, bb);
            }
        }

        cp_wait<0>();
        __syncthreads();   // tile j+1 ready; all warps done with buffer cur
    }

    // ---- normalize + store y fp16, pair-permuted (feeds final GEMM) ----
    float inv0 = 1.f / l0, inv1 = 1.f / l1;
    __half* y0 = Y + (size_t)(b * T_SZ + bi * 128 + warp * 16 + lr) * 2048 + h * 128;
    __half* y1 = y0 + 8 * 2048;
#pragma unroll
    for (int nf = 0; nf < 16; nf++) {
        int hc = nf * 8 + 2 * lc;
        int colw = (hc & ~15) + pslot((hc >> 1) & 7) * 2;
        *(half2*)(y0 + colw) = __halves2half2(__float2half(o[nf][0] * inv0),
                                              __float2half(o[nf][1] * inv0));
        *(half2*)(y1 + colw) = __halves2half2(__float2half(o[nf][2] * inv1),
                                              __float2half(o[nf][3] * inv1));
    }
}

// ---------------------------------------------------------------------------
extern "C" void kernel_launch(void* const* d_in, const int* in_sizes, int n_in,
                              void* d_out, int out_size) {
    const float* x  = (const float*)d_in[0];
    const float* wq = (const float*)d_in[1];
    const float* wk = (const float*)d_in[2];
    const float* wv = (const float*)d_in[3];
    const float* wo = (const float*)d_in[4];
    float* out = (float*)d_out;

    __half *qp, *kp, *vp, *yp, *xh, *wqkvT, *woT;
    cudaGetSymbolAddress((void**)&qp,    g_q);
    cudaGetSymbolAddress((void**)&kp,    g_k);
    cudaGetSymbolAddress((void**)&vp,    g_v);
    cudaGetSymbolAddress((void**)&yp,    g_y);
    cudaGetSymbolAddress((void**)&xh,    g_xh);
    cudaGetSymbolAddress((void**)&wqkvT, g_wqkvT);
    cudaGetSymbolAddress((void**)&woT,   g_woT);

    cudaFuncSetAttribute(gemm_h<false>, cudaFuncAttributeMaxDynamicSharedMemorySize, GEMM_SMEM);
    cudaFuncSetAttribute(gemm_h<true>,  cudaFuncAttributeMaxDynamicSharedMemorySize, GEMM_SMEM);
    cudaFuncSetAttribute(flash_h, cudaFuncAttributeMaxDynamicSharedMemorySize, FA_SMEM);

    dim3 tb(32, 8);
    transpose_h<<<dim3(2048 / 32, 2048 / 32), tb>>>(wq, wqkvT,               2048, 2048);
    transpose_h<<<dim3(512  / 32, 2048 / 32), tb>>>(wk, wqkvT + 2048 * 2048, 2048, 512);
    transpose_h<<<dim3(512  / 32, 2048 / 32), tb>>>(wv, wqkvT + 2560 * 2048, 2048, 512);
    transpose_h<<<dim3(2048 / 32, 2048 / 32), tb>>>(wo, woT,                 2048, 2048);

    conv_x<<<(MR * 2048 / 4 + 255) / 256, 256>>>(x, xh, MR * 2048 / 4);

    // Fused QKV projection (N = 3072); q,k head-permuted fp16; v natural fp16
    gemm_h<true><<<dim3(3072 / BN, MR / BM), 256, GEMM_SMEM>>>(
        xh, wqkvT, nullptr, qp, kp, vp, 3072);

    rope_h<<<(MR * NH  * 64 + 255) / 256, 256>>>(qp, NH);
    rope_h<<<(MR * NKV * 64 + 255) / 256, 256>>>(kp, NKV);

    // fp16 tensor-core causal GQA flash attention (KV tile 128, double-buffered)
    flash_h<<<dim3(T_SZ / 128, B_SZ * NH), 256, FA_SMEM>>>(qp, kp, vp, yp);

    // Output projection (fp32 out)
    gemm_h<false><<<dim3(2048 / BN, MR / BM), 256, GEMM_SMEM>>>(
        yp, woT, out, nullptr, nullptr, nullptr, 2048);
}

// round 17
// speedup vs baseline: 1.1682x; 1.1064x over previous
#include <cuda_runtime.h>
#include <cuda_fp16.h>
#include <math.h>
#include <cstdint>

#define B_SZ 2
#define T_SZ 2048
#define NH   16
#define NKV  4
#define HD   128
#define MR   (B_SZ * T_SZ)   // 4096 rows
#define KC   2048            // inner dim (halves) of projection GEMMs

// ---------------- scratch (__device__ globals: allocation-free rule) --------
__device__ __half g_q   [MR * NH  * HD];   // head-dim pair-permuted, rope applied
__device__ __half g_k   [MR * NKV * HD];   // head-dim pair-permuted, rope applied
__device__ __half g_v   [MR * NKV * HD];   // natural
__device__ __half g_y   [MR * NH  * HD];   // pair-permuted (feeds final GEMM)
__device__ __half g_xh  [MR * 2048];       // x, fp16 + pair-permuted
__device__ __half g_wqkvT[3072 * 2048];    // [wq;wk;wv]^T, fp16 + pair-permuted
__device__ __half g_woT [2048 * 2048];     // wo^T, fp16 + pair-permuted
__device__ float  g_rtab[T_SZ * 64 * 2];   // [t][dp] -> (cos, sin)

// pair-permutation within each 16-half k-group:
//   pair p (0..7) -> slot ((p&3)<<1)|(p>>2); element k -> k' below
__device__ __forceinline__ int pslot(int p) { return ((p & 3) << 1) | (p >> 2); }
__device__ __forceinline__ int kperm(int k) {
    return (k & ~15) | (pslot((k >> 1) & 7) << 1) | (k & 1);
}

// ---------------- PTX helpers (baseline compute_103-safe) -------------------
__device__ __forceinline__ void cp16(uint32_t s, const void* g) {
    asm volatile("cp.async.cg.shared.global [%0], [%1], 16;" :: "r"(s), "l"(g));
}
__device__ __forceinline__ void cp_commit() {
    asm volatile("cp.async.commit_group;" ::: "memory");
}
template <int N> __device__ __forceinline__ void cp_wait() {
    asm volatile("cp.async.wait_group %0;" :: "n"(N) : "memory");
}
// m16n8k16 fp16 mma, fp32 accum
__device__ __forceinline__ void mma_f16(float* c, const uint32_t* a, const uint32_t* b) {
    asm volatile(
        "mma.sync.aligned.m16n8k16.row.col.f32.f16.f16.f32 "
        "{%0,%1,%2,%3}, {%4,%5,%6,%7}, {%8,%9}, {%0,%1,%2,%3};"
        : "+f"(c[0]), "+f"(c[1]), "+f"(c[2]), "+f"(c[3])
        : "r"(a[0]), "r"(a[1]), "r"(a[2]), "r"(a[3]), "r"(b[0]), "r"(b[1]));
}
__device__ __forceinline__ uint32_t f2h2(float a, float b) {
    half2 h = __floats2half2_rn(a, b);
    return *(uint32_t*)&h;
}

// ---------------------------------------------------------------------------
// fp16 mma GEMM: C[M,N] = A[M,2048] @ BT[N,2048]^T (both fp16, pair-permuted k)
// CTA 128(M) x 256(N) x 64(K halves); 256 thr, 8 warps (2m x 4n), warp 64x64.
// 3-stage cp.async pipeline, one sync per iter (32 iters).
// SPLIT: route 64-col groups to q/k (rope applied + head-permuted) and v.
// ---------------------------------------------------------------------------
#define BM 128
#define BN 256
#define BK 64
#define PADH 72                               // halves per stage row
#define STG_HALVES ((BM + BN) * PADH)         // 27648
#define GEMM_SMEM  (3 * STG_HALVES * 2)       // 165888 B

__device__ __forceinline__ void g_fill(uint32_t smb, int st, int ck, int tid,
                                       const __half* Ab, const __half* Bb) {
    uint32_t sa = smb + st * (STG_HALVES * 2);
    uint32_t sb = sa + BM * PADH * 2;
    const __half* Ac = Ab + ck * BK;
    const __half* Bc = Bb + ck * BK;
#pragma unroll
    for (int u = 0; u < 4; u++) {           // A: 128 rows x 8 cp16
        int idx = u * 256 + tid;
        int r = idx >> 3, c8 = (idx & 7) * 8;
        cp16(sa + (r * PADH + c8) * 2, Ac + (size_t)r * KC + c8);
    }
#pragma unroll
    for (int u = 0; u < 8; u++) {           // B: 256 rows x 8 cp16
        int idx = u * 256 + tid;
        int r = idx >> 3, c8 = (idx & 7) * 8;
        cp16(sb + (r * PADH + c8) * 2, Bc + (size_t)r * KC + c8);
    }
    cp_commit();
}

template <bool SPLIT>
__global__ void __launch_bounds__(256, 1)
gemm_h(const __half* __restrict__ A, const __half* __restrict__ BT,
       float* __restrict__ Cf, __half* __restrict__ Cq,
       __half* __restrict__ Ck, __half* __restrict__ Cv,
       const float* __restrict__ tab, int N) {
    extern __shared__ __half smh[];
    uint32_t smb = (uint32_t)__cvta_generic_to_shared(smh);

    const int tid  = threadIdx.x;
    const int lane = tid & 31;
    const int warp = tid >> 5;
    const int wm   = (warp >> 2) * 64;
    const int wn   = (warp & 3) * 64;
    const int bm   = blockIdx.y * BM;
    const int bn   = blockIdx.x * BN;

    const __half* Ab = A  + (size_t)bm * KC;
    const __half* Bb = BT + (size_t)bn * KC;

    float acc[4][8][4];
#pragma unroll
    for (int i = 0; i < 4; i++)
#pragma unroll
        for (int j = 0; j < 8; j++)
#pragma unroll
            for (int r = 0; r < 4; r++) acc[i][j][r] = 0.f;

    g_fill(smb, 0, 0, tid, Ab, Bb);
    g_fill(smb, 1, 1, tid, Ab, Bb);

    const int lr = lane >> 2;
    const int lc = lane & 3;
    const int NCK = KC / BK;   // 32

    for (int i = 0; i < NCK; i++) {
        cp_wait<1>();
        __syncthreads();   // stage i ready AND all warps done with stage (i-1)%3
        if (i + 2 < NCK) g_fill(smb, (i + 2) % 3, i + 2, tid, Ab, Bb);

        const __half* As = smh + (i % 3) * STG_HALVES;
        const __half* Bs = As + BM * PADH;

#pragma unroll
        for (int ks = 0; ks < 4; ks++) {      // four k16 chunks per BK=64
            uint32_t a[4][4], b[8][2];
#pragma unroll
            for (int mf = 0; mf < 4; mf++) {
                uint2 v0 = *(const uint2*)(As + (wm + mf * 16 + lr) * PADH + ks * 16 + 4 * lc);
                uint2 v1 = *(const uint2*)(As + (wm + mf * 16 + lr + 8) * PADH + ks * 16 + 4 * lc);
                a[mf][0] = v0.x; a[mf][1] = v1.x;
                a[mf][2] = v0.y; a[mf][3] = v1.y;
            }
#pragma unroll
            for (int nf = 0; nf < 8; nf++) {
                uint2 v = *(const uint2*)(Bs + (wn + nf * 8 + lr) * PADH + ks * 16 + 4 * lc);
                b[nf][0] = v.x; b[nf][1] = v.y;
            }
#pragma unroll
            for (int mf = 0; mf < 4; mf++)
#pragma unroll
                for (int nf = 0; nf < 8; nf++)
                    mma_f16(acc[mf][nf], a[mf], b[nf]);
        }
    }

    // ---- epilogue ----
    const int colbase = bn + wn;    // multiple of 64
    if (!SPLIT) {
#pragma unroll
        for (int mf = 0; mf < 4; mf++) {
            int row0 = bm + wm + mf * 16 + lr;
#pragma unroll
            for (int nf = 0; nf < 8; nf++) {
                int col = colbase + nf * 8 + lc * 2;
                *(float2*)(Cf + (size_t)row0 * N + col) =
                    make_float2(acc[mf][nf][0], acc[mf][nf][1]);
                *(float2*)(Cf + (size_t)(row0 + 8) * N + col) =
                    make_float2(acc[mf][nf][2], acc[mf][nf][3]);
            }
        }
    } else {
        // cross-warp exchange: partner warp (warp^1) holds same rows, cols +-64
        // (exactly the rope pair). Reuse stage smem (166KB >= 128KB needed).
        __syncthreads();                       // all warps done with stage smem
        float* ex = (float*)smh;
        float* myw = ex + warp * 4096 + lane;
#pragma unroll
        for (int mf = 0; mf < 4; mf++)
#pragma unroll
            for (int nf = 0; nf < 8; nf++)
#pragma unroll
                for (int r = 0; r < 4; r++)
                    myw[(mf * 32 + nf * 4 + r) * 32] = acc[mf][nf][r];
        __syncthreads();
        const float* pw = ex + (warp ^ 1) * 4096 + lane;

        __half* dst; int ldc; int cb; bool isqk;
        if (colbase < 2048)      { dst = Cq; ldc = 2048; cb = colbase;        isqk = true; }
        else if (colbase < 2560) { dst = Ck; ldc = 512;  cb = colbase - 2048; isqk = true; }
        else                     { dst = Cv; ldc = 512;  cb = colbase - 2560; isqk = false; }
        const float sgn = (warp & 1) ? 1.f : -1.f;   // low half: -sin, high: +sin

#pragma unroll
        for (int mf = 0; mf < 4; mf++) {
            int row0 = bm + wm + mf * 16 + lr;
            int t0 = row0 & (T_SZ - 1);        // token index (row+8 same batch)
#pragma unroll
            for (int nf = 0; nf < 8; nf++) {
                int col = cb + nf * 8 + lc * 2;
                float v0 = acc[mf][nf][0], v1 = acc[mf][nf][1];
                float v2 = acc[mf][nf][2], v3 = acc[mf][nf][3];
                if (isqk) {
                    int dp = col & 63;
                    float2 cs00 = *(const float2*)(tab + ((size_t)t0 * 64 + dp) * 2);
                    float2 cs01 = *(const float2*)(tab + ((size_t)t0 * 64 + dp + 1) * 2);
                    float2 cs10 = *(const float2*)(tab + ((size_t)(t0 + 8) * 64 + dp) * 2);
                    float2 cs11 = *(const float2*)(tab + ((size_t)(t0 + 8) * 64 + dp + 1) * 2);
                    float p0 = pw[(mf * 32 + nf * 4 + 0) * 32];
                    float p1 = pw[(mf * 32 + nf * 4 + 1) * 32];
                    float p2 = pw[(mf * 32 + nf * 4 + 2) * 32];
                    float p3 = pw[(mf * 32 + nf * 4 + 3) * 32];
                    v0 = v0 * cs00.x + sgn * p0 * cs00.y;
                    v1 = v1 * cs01.x + sgn * p1 * cs01.y;
                    v2 = v2 * cs10.x + sgn * p2 * cs10.y;
                    v3 = v3 * cs11.x + sgn * p3 * cs11.y;
                }
                int colw = col;
                if (isqk) {
                    int hb = col & ~127, hc = col & 127;
                    colw = hb + (hc & ~15) + pslot((hc >> 1) & 7) * 2;
                }
                half2 v01 = __halves2half2(__float2half(v0), __float2half(v1));
                half2 v23 = __halves2half2(__float2half(v2), __float2half(v3));
                *(half2*)(dst + (size_t)row0 * ldc + colw)       = v01;
                *(half2*)(dst + (size_t)(row0 + 8) * ldc + colw) = v23;
            }
        }
    }
}

// ---------------------------------------------------------------------------
// cos/sin table: tab[t][dp] = (cos(t*invf), sin(t*invf)), invf = 10000^(-dp/64)
// ---------------------------------------------------------------------------
__global__ void rope_tab(float* __restrict__ tab) {
    int i = blockIdx.x * blockDim.x + threadIdx.x;
    if (i >= T_SZ * 64) return;
    int t = i >> 6, dp = i & 63;
    float inv_freq = powf(10000.0f, -(float)(2 * dp) * (1.0f / 128.0f));
    float sv, cv;
    sincosf((float)t * inv_freq, &sv, &cv);
    tab[i * 2]     = cv;
    tab[i * 2 + 1] = sv;
}

// ---------------------------------------------------------------------------
// Weight transpose + fp16 + pair-permute: WT[n][kperm(k)] = h(W[k][n])
// ---------------------------------------------------------------------------
__global__ void transpose_h(const float* __restrict__ W, __half* __restrict__ WT,
                            int K, int N) {
    __shared__ float t[32][33];
    int n0 = blockIdx.x * 32, k0 = blockIdx.y * 32;
    int tx = threadIdx.x, ty = threadIdx.y;
#pragma unroll
    for (int i = 0; i < 4; i++)
        t[ty + 8 * i][tx] = W[(size_t)(k0 + ty + 8 * i) * N + n0 + tx];
    __syncthreads();
    int kp = kperm(k0 + tx);
#pragma unroll
    for (int i = 0; i < 4; i++)
        WT[(size_t)(n0 + ty + 8 * i) * K + kp] = __float2half(t[tx][ty + 8 * i]);
}

// x -> fp16, pair-permuted
__global__ void conv_x(const float* __restrict__ X, __half* __restrict__ XH, int n4) {
    int i = blockIdx.x * blockDim.x + threadIdx.x;
    if (i >= n4) return;
    float4 v = ((const float4*)X)[i];
    int f0 = i * 4;                       // multiple of 4 -> pair index even
    int base = f0 & ~15;
    int p0 = (f0 >> 1) & 7;               // even
    int s0 = pslot(p0), s1 = pslot(p0 + 1);
    *(half2*)(XH + base + s0 * 2) = __halves2half2(__float2half(v.x), __float2half(v.y));
    *(half2*)(XH + base + s1 * 2) = __halves2half2(__float2half(v.z), __float2half(v.w));
}

// ---------------------------------------------------------------------------
// fp16 tensor-core flash attention (m16n8k16), causal, GQA.
// CTA: 128 queries; KV tiles of 128; 8 warps, warp = 16 q rows x 128 keys.
// Double-buffered K/Vt; register-resident P; diagonal-tile-only masking.
// Smem (halves): K0 @0 (128x136), K1 @17408, Vt0 @34816 (128x136), Vt1 @52224.
// Total 69632 halves = 139264 B.
// ---------------------------------------------------------------------------
#define KPADH 136
#define VPADH 136
#define KBUF  17408
#define FA_SMEM (69632 * 2)

__global__ void __launch_bounds__(256, 1)
flash_h(const __half* __restrict__ Q, const __half* __restrict__ K,
        const __half* __restrict__ V, __half* __restrict__ Y) {
    extern __shared__ __half smh[];
    uint32_t smb = (uint32_t)__cvta_generic_to_shared(smh);

    const int bi  = gridDim.x - 1 - blockIdx.x;   // big tiles first
    const int bh  = blockIdx.y;
    const int b   = bh >> 4, h = bh & 15;
    const int kvh = h >> 2;
    const int tid = threadIdx.x;
    const int warp = tid >> 5, lane = tid & 31;
    const int lr = lane >> 2, lc = lane & 3;

    const __half* kg0 = K + (size_t)(b * T_SZ) * 512 + kvh * 128;
    const __half* vg0 = V + (size_t)(b * T_SZ) * 512 + kvh * 128;

    // stage Q tile (fp16, pair-permuted) into smem @0: 128 x 128 halves
    const __half* qg = Q + (size_t)(b * T_SZ + bi * 128) * 2048 + h * 128;
#pragma unroll
    for (int it = 0; it < 8; it++) {
        int idx = it * 256 + tid;
        int r = idx >> 4, c8 = (idx & 15) * 8;
        cp16(smb + (r * KPADH + c8) * 2, qg + (size_t)r * 2048 + c8);
    }
    cp_commit();
    cp_wait<0>();
    __syncthreads();

    uint32_t qa[8][4];
#pragma unroll
    for (int ck = 0; ck < 8; ck++) {
        uint2 v0 = *(const uint2*)(smh + (warp * 16 + lr) * KPADH + ck * 16 + 4 * lc);
        uint2 v1 = *(const uint2*)(smh + (warp * 16 + lr + 8) * KPADH + ck * 16 + 4 * lc);
        qa[ck][0] = v0.x; qa[ck][1] = v1.x;
        qa[ck][2] = v0.y; qa[ck][3] = v1.y;
    }
    __syncthreads();   // all warps done reading Qs before K fills overwrite it

    // V-transpose thread mapping (fixed per thread)
    const int vd = (warp & 3) * 32 + lane;      // d: 0..127
    const int vt0 = (warp >> 2) * 4;            // t start: 0 or 4

    // ---- prologue: fill buffer 0 with kv tile 0 (128 rows) ----
    {
        const __half* kg = kg0;
#pragma unroll
        for (int it = 0; it < 8; it++) {
            int idx = it * 256 + tid;
            int r = idx >> 4, c8 = (idx & 15) * 8;
            cp16(smb + (r * KPADH + c8) * 2, kg + (size_t)r * 512 + c8);
        }
        cp_commit();
        const __half* vg = vg0;
        __half* Vt = smh + 2 * KBUF;
#pragma unroll
        for (int it = 0; it < 16; it++) {
            int t4 = vt0 + it * 8;
            __half v0 = vg[(size_t)(t4 + 0) * 512 + vd];
            __half v1 = vg[(size_t)(t4 + 1) * 512 + vd];
            __half v2 = vg[(size_t)(t4 + 2) * 512 + vd];
            __half v3 = vg[(size_t)(t4 + 3) * 512 + vd];
            int p = t4 >> 1;
            int chb = (p >> 3) * 16;
            *(half2*)(Vt + vd * VPADH + chb + pslot(p & 7) * 2) = __halves2half2(v0, v1);
            *(half2*)(Vt + vd * VPADH + chb + pslot((p + 1) & 7) * 2) = __halves2half2(v2, v3);
        }
        cp_wait<0>();
        __syncthreads();
    }

    float o[16][4];
#pragma unroll
    for (int nf = 0; nf < 16; nf++)
        o[nf][0] = o[nf][1] = o[nf][2] = o[nf][3] = 0.f;
    float m0 = -1e30f, m1 = -1e30f, l0 = 0.f, l1 = 0.f;

    const float sc = 0.08838834764831845f;   // 1/sqrt(128)
    const int rlo = bi * 128 + warp * 16 + lr;

    for (int j = 0; j <= bi; j++) {
        const int cur = j & 1;

        // ---- prefetch tile j+1 into the other buffer ----
        if (j < bi) {
            const int nx = cur ^ 1;
            const __half* kg = kg0 + (size_t)(j + 1) * 128 * 512;
#pragma unroll
            for (int it = 0; it < 8; it++) {
                int idx = it * 256 + tid;
                int r = idx >> 4, c8 = (idx & 15) * 8;
                cp16(smb + (nx * KBUF + r * KPADH + c8) * 2, kg + (size_t)r * 512 + c8);
            }
            cp_commit();
            const __half* vg = vg0 + (size_t)(j + 1) * 128 * 512;
            __half* Vt = smh + 2 * KBUF + nx * KBUF;
#pragma unroll
            for (int it = 0; it < 16; it++) {
                int t4 = vt0 + it * 8;
                __half v0 = vg[(size_t)(t4 + 0) * 512 + vd];
                __half v1 = vg[(size_t)(t4 + 1) * 512 + vd];
                __half v2 = vg[(size_t)(t4 + 2) * 512 + vd];
                __half v3 = vg[(size_t)(t4 + 3) * 512 + vd];
                int p = t4 >> 1;
                int chb = (p >> 3) * 16;
                *(half2*)(Vt + vd * VPADH + chb + pslot(p & 7) * 2) = __halves2half2(v0, v1);
                *(half2*)(Vt + vd * VPADH + chb + pslot((p + 1) & 7) * 2) = __halves2half2(v2, v3);
            }
        }

        const __half* Ks = smh + cur * KBUF;
        const __half* Vc = smh + 2 * KBUF + cur * KBUF;

        // ---- S = Q K^T (warp: 16 x 128), two nf-halves of 8 accumulators ----
        float sa[16][4];
#pragma unroll
        for (int nf = 0; nf < 16; nf++)
            sa[nf][0] = sa[nf][1] = sa[nf][2] = sa[nf][3] = 0.f;
#pragma unroll
        for (int half = 0; half < 2; half++) {
#pragma unroll
            for (int ck = 0; ck < 8; ck++) {
                uint32_t bf[8][2];
#pragma unroll
                for (int nf = 0; nf < 8; nf++) {
                    uint2 v = *(const uint2*)(Ks + ((half * 8 + nf) * 8 + lr) * KPADH + ck * 16 + 4 * lc);
                    bf[nf][0] = v.x; bf[nf][1] = v.y;
                }
#pragma unroll
                for (int nf = 0; nf < 8; nf++)
                    mma_f16(sa[half * 8 + nf], qa[ck], bf[nf]);
            }
        }

        // ---- scale + causal mask (diagonal tile only) ----
        const bool domask = (j == bi);
#pragma unroll
        for (int nf = 0; nf < 16; nf++) {
            sa[nf][0] *= sc; sa[nf][1] *= sc;
            sa[nf][2] *= sc; sa[nf][3] *= sc;
            if (domask) {
                int c0 = j * 128 + nf * 8 + 2 * lc;
                if (c0 > rlo)         sa[nf][0] = -1e30f;
                if (c0 + 1 > rlo)     sa[nf][1] = -1e30f;
                if (c0 > rlo + 8)     sa[nf][2] = -1e30f;
                if (c0 + 1 > rlo + 8) sa[nf][3] = -1e30f;
            }
        }

        // ---- online softmax (2 rows/thread, quad reduce); P stays in sa ----
        float mx0 = -1e30f, mx1 = -1e30f;
#pragma unroll
        for (int nf = 0; nf < 16; nf++) {
            mx0 = fmaxf(mx0, fmaxf(sa[nf][0], sa[nf][1]));
            mx1 = fmaxf(mx1, fmaxf(sa[nf][2], sa[nf][3]));
        }
        mx0 = fmaxf(mx0, __shfl_xor_sync(0xffffffffu, mx0, 1));
        mx0 = fmaxf(mx0, __shfl_xor_sync(0xffffffffu, mx0, 2));
        mx1 = fmaxf(mx1, __shfl_xor_sync(0xffffffffu, mx1, 1));
        mx1 = fmaxf(mx1, __shfl_xor_sync(0xffffffffu, mx1, 2));

        float mn0 = fmaxf(m0, mx0), mn1 = fmaxf(m1, mx1);
        float al0 = __expf(m0 - mn0), al1 = __expf(m1 - mn1);
        float s0 = 0.f, s1 = 0.f;
#pragma unroll
        for (int nf = 0; nf < 16; nf++) {
            float p0 = __expf(sa[nf][0] - mn0);
            float p1 = __expf(sa[nf][1] - mn0);
            float p2 = __expf(sa[nf][2] - mn1);
            float p3 = __expf(sa[nf][3] - mn1);
            s0 += p0 + p1; s1 += p2 + p3;
            sa[nf][0] = p0; sa[nf][1] = p1; sa[nf][2] = p2; sa[nf][3] = p3;
        }
        s0 += __shfl_xor_sync(0xffffffffu, s0, 1);
        s0 += __shfl_xor_sync(0xffffffffu, s0, 2);
        s1 += __shfl_xor_sync(0xffffffffu, s1, 1);
        s1 += __shfl_xor_sync(0xffffffffu, s1, 2);
        l0 = l0 * al0 + s0; m0 = mn0;
        l1 = l1 * al1 + s1; m1 = mn1;
#pragma unroll
        for (int nf = 0; nf < 16; nf++) {
            o[nf][0] *= al0; o[nf][1] *= al0;
            o[nf][2] *= al1; o[nf][3] *= al1;
        }

        // ---- O += P V (warp: 16 x 128); P packed from registers ----
#pragma unroll
        for (int ck = 0; ck < 8; ck++) {
            uint32_t pa[4];
            pa[0] = f2h2(sa[2 * ck][0],     sa[2 * ck][1]);
            pa[1] = f2h2(sa[2 * ck][2],     sa[2 * ck][3]);
            pa[2] = f2h2(sa[2 * ck + 1][0], sa[2 * ck + 1][1]);
            pa[3] = f2h2(sa[2 * ck + 1][2], sa[2 * ck + 1][3]);
#pragma unroll
            for (int nf = 0; nf < 16; nf++) {
                uint2 bv = *(const uint2*)(Vc + (nf * 8 + lr) * VPADH + ck * 16 + 4 * lc);
                uint32_t bb[2] = {bv.x, bv.y};
                mma_f16(o[nf], pa, bb);
            }
        }

        cp_wait<0>();
        __syncthreads();   // tile j+1 ready; all warps done with buffer cur
    }

    // ---- normalize + store y fp16, pair-permuted (feeds final GEMM) ----
    float inv0 = 1.f / l0, inv1 = 1.f / l1;
    __half* y0 = Y + (size_t)(b * T_SZ + bi * 128 + warp * 16 + lr) * 2048 + h * 128;
    __half* y1 = y0 + 8 * 2048;
#pragma unroll
    for (int nf = 0; nf < 16; nf++) {
        int hc = nf * 8 + 2 * lc;
        int colw = (hc & ~15) + pslot((hc >> 1) & 7) * 2;
        *(half2*)(y0 + colw) = __halves2half2(__float2half(o[nf][0] * inv0),
                                              __float2half(o[nf][1] * inv0));
        *(half2*)(y1 + colw) = __halves2half2(__float2half(o[nf][2] * inv1),
                                              __float2half(o[nf][3] * inv1));
    }
}

// ---------------------------------------------------------------------------
extern "C" void kernel_launch(void* const* d_in, const int* in_sizes, int n_in,
                              void* d_out, int out_size) {
    const float* x  = (const float*)d_in[0];
    const float* wq = (const float*)d_in[1];
    const float* wk = (const float*)d_in[2];
    const float* wv = (const float*)d_in[3];
    const float* wo = (const float*)d_in[4];
    float* out = (float*)d_out;

    __half *qp, *kp, *vp, *yp, *xh, *wqkvT, *woT;
    float* rtab;
    cudaGetSymbolAddress((void**)&qp,    g_q);
    cudaGetSymbolAddress((void**)&kp,    g_k);
    cudaGetSymbolAddress((void**)&vp,    g_v);
    cudaGetSymbolAddress((void**)&yp,    g_y);
    cudaGetSymbolAddress((void**)&xh,    g_xh);
    cudaGetSymbolAddress((void**)&wqkvT, g_wqkvT);
    cudaGetSymbolAddress((void**)&woT,   g_woT);
    cudaGetSymbolAddress((void**)&rtab,  g_rtab);

    cudaFuncSetAttribute(gemm_h<false>, cudaFuncAttributeMaxDynamicSharedMemorySize, GEMM_SMEM);
    cudaFuncSetAttribute(gemm_h<true>,  cudaFuncAttributeMaxDynamicSharedMemorySize, GEMM_SMEM);
    cudaFuncSetAttribute(flash_h, cudaFuncAttributeMaxDynamicSharedMemorySize, FA_SMEM);

    dim3 tb(32, 8);
    transpose_h<<<dim3(2048 / 32, 2048 / 32), tb>>>(wq, wqkvT,               2048, 2048);
    transpose_h<<<dim3(512  / 32, 2048 / 32), tb>>>(wk, wqkvT + 2048 * 2048, 2048, 512);
    transpose_h<<<dim3(512  / 32, 2048 / 32), tb>>>(wv, wqkvT + 2560 * 2048, 2048, 512);
    transpose_h<<<dim3(2048 / 32, 2048 / 32), tb>>>(wo, woT,                 2048, 2048);

    conv_x<<<(MR * 2048 / 4 + 255) / 256, 256>>>(x, xh, MR * 2048 / 4);
    rope_tab<<<(T_SZ * 64 + 255) / 256, 256>>>(rtab);

    // Fused QKV projection + RoPE (N = 3072); q,k rope+head-permuted; v natural
    gemm_h<true><<<dim3(3072 / BN, MR / BM), 256, GEMM_SMEM>>>(
        xh, wqkvT, nullptr, qp, kp, vp, rtab, 3072);

    // fp16 tensor-core causal GQA flash attention (KV tile 128, double-buffered)
    flash_h<<<dim3(T_SZ / 128, B_SZ * NH), 256, FA_SMEM>>>(qp, kp, vp, yp);

    // Output projection (fp32 out)
    gemm_h<false><<<dim3(2048 / BN, MR / BM), 256, GEMM_SMEM>>>(
        yp, woT, out, nullptr, nullptr, nullptr, nullptr, 2048);
}